// round 9
// baseline (speedup 1.0000x reference)
#include <cuda_runtime.h>

// FINAL — roofline-saturated streaming kernel.
// B=16, mask (16,2,512,512) -bilinear x2-> (16,2,1024,1024)
// fused = x_mask*xl + y_mask*yl (3 ch), out = relu(conv1x1(fused)+b)
// d_out: out (48 planes) | x_mask (16 planes) | y_mask (16 planes), plane=1024*1024
//
// Design (validated by R2-R8 sweep):
//  - single fused pass: 736 MiB compulsory traffic, zero intermediates
//  - one float4 group (4 out pixels) per thread; warp-contiguous -> all big
//    LDG/STG are 512B fully-coalesced transactions
//  - 6 CTAs/SM (regs 40, occ ~64%): measured optimum. regs=32 remat-regressed,
//    2x unroll occ-regressed.
//  - __ldcs/__stcs on one-touch streams; mask loads stay L1/L2-resident
//  - mask (k0,k0+1) as aligned float2 pair loads
// Measured: 109.9us kernel, 82.4% DRAM (6530 GB/s) = mixed r/w turnaround ceiling.

#define HS 512
#define WS 512
#define HU 1024
#define WU 1024

__global__ __launch_bounds__(256, 6)
void fused_upsample_blend_conv(const float* __restrict__ mask,
                               const float* __restrict__ xl,
                               const float* __restrict__ yl,
                               const float* __restrict__ cw,
                               const float* __restrict__ cb,
                               float* __restrict__ out)
{
    const int idx = blockIdx.x * blockDim.x + threadIdx.x;
    // idx -> (b, h, w4): w4 in [0,256), h in [0,1024), b in [0,16)
    const int w4 = idx & 255;
    const int h  = (idx >> 8) & 1023;
    const int b  = idx >> 18;

    const int w = w4 << 2;
    const long plane = (long)HU * WU;
    const long pix   = (long)h * WU + w;
    const float* xb = xl + (long)b * 3 * plane;
    const float* yb = yl + (long)b * 3 * plane;

    // ---- streaming loads first (touched once; evict-first) ----
    const float4 a0 = __ldcs((const float4*)(xb + 0 * plane + pix));
    const float4 a1 = __ldcs((const float4*)(xb + 1 * plane + pix));
    const float4 a2 = __ldcs((const float4*)(xb + 2 * plane + pix));
    const float4 g0 = __ldcs((const float4*)(yb + 0 * plane + pix));
    const float4 g1 = __ldcs((const float4*)(yb + 1 * plane + pix));
    const float4 g2 = __ldcs((const float4*)(yb + 2 * plane + pix));

    // ---- bilinear mask upsample (half-pixel centers, scale 2) ----
    // row h samples source row 0.5h-0.25:
    //   even h=2j: 0.75*row[j] + 0.25*row[j-1] (clamped)
    //   odd  h=2j+1: 0.75*row[j] + 0.25*row[j+1] (clamped)
    const int hj = h >> 1;
    const int r1 = hj;
    const int r2 = (h & 1) ? min(hj + 1, HS - 1) : max(hj - 1, 0);

    const int k0  = w4 << 1;              // even, 0..510
    const int cm1 = max(k0 - 1, 0);
    const int cp2 = min(k0 + 2, WS - 1);

    const float* m0r1 = mask + (((long)b * 2 + 0) * HS + r1) * WS;
    const float* m0r2 = mask + (((long)b * 2 + 0) * HS + r2) * WS;
    const float* m1r1 = mask + (((long)b * 2 + 1) * HS + r1) * WS;
    const float* m1r2 = mask + (((long)b * 2 + 1) * HS + r2) * WS;

    // pair loads: (k0, k0+1) is an aligned float2 (k0 even)
    const float2 p01 = __ldg((const float2*)(m0r1 + k0));
    const float2 p02 = __ldg((const float2*)(m0r2 + k0));
    const float2 p11 = __ldg((const float2*)(m1r1 + k0));
    const float2 p12 = __ldg((const float2*)(m1r2 + k0));

    // vertical interp at 4 source columns, both mask channels (L1/L2-resident)
    const float v0a = 0.75f * __ldg(m0r1 + cm1) + 0.25f * __ldg(m0r2 + cm1);
    const float v0b = 0.75f * p01.x + 0.25f * p02.x;
    const float v0c = 0.75f * p01.y + 0.25f * p02.y;
    const float v0d = 0.75f * __ldg(m0r1 + cp2) + 0.25f * __ldg(m0r2 + cp2);

    const float v1a = 0.75f * __ldg(m1r1 + cm1) + 0.25f * __ldg(m1r2 + cm1);
    const float v1b = 0.75f * p11.x + 0.25f * p12.x;
    const float v1c = 0.75f * p11.y + 0.25f * p12.y;
    const float v1d = 0.75f * __ldg(m1r1 + cp2) + 0.25f * __ldg(m1r2 + cp2);

    // horizontal: out 2k -> .75 v[k] + .25 v[k-1]; out 2k+1 -> .75 v[k] + .25 v[k+1]
    float4 xm, ym;
    xm.x = 0.75f * v0b + 0.25f * v0a;
    xm.y = 0.75f * v0b + 0.25f * v0c;
    xm.z = 0.75f * v0c + 0.25f * v0b;
    xm.w = 0.75f * v0c + 0.25f * v0d;

    ym.x = 0.75f * v1b + 0.25f * v1a;
    ym.y = 0.75f * v1b + 0.25f * v1c;
    ym.z = 0.75f * v1c + 0.25f * v1b;
    ym.w = 0.75f * v1c + 0.25f * v1d;

    // ---- fuse (consumes the DRAM loads) ----
    float4 f0, f1, f2;
    f0.x = xm.x * a0.x + ym.x * g0.x;  f0.y = xm.y * a0.y + ym.y * g0.y;
    f0.z = xm.z * a0.z + ym.z * g0.z;  f0.w = xm.w * a0.w + ym.w * g0.w;
    f1.x = xm.x * a1.x + ym.x * g1.x;  f1.y = xm.y * a1.y + ym.y * g1.y;
    f1.z = xm.z * a1.z + ym.z * g1.z;  f1.w = xm.w * a1.w + ym.w * g1.w;
    f2.x = xm.x * a2.x + ym.x * g2.x;  f2.y = xm.y * a2.y + ym.y * g2.y;
    f2.z = xm.z * a2.z + ym.z * g2.z;  f2.w = xm.w * a2.w + ym.w * g2.w;

    // conv params (uniform broadcast, L1-resident)
    const float w00 = __ldg(cw + 0), w01 = __ldg(cw + 1), w02 = __ldg(cw + 2);
    const float w10 = __ldg(cw + 3), w11 = __ldg(cw + 4), w12 = __ldg(cw + 5);
    const float w20 = __ldg(cw + 6), w21 = __ldg(cw + 7), w22 = __ldg(cw + 8);
    const float bb0 = __ldg(cb + 0), bb1 = __ldg(cb + 1), bb2 = __ldg(cb + 2);

    float4 o0, o1, o2;
    o0.x = fmaxf(w00 * f0.x + w01 * f1.x + w02 * f2.x + bb0, 0.f);
    o0.y = fmaxf(w00 * f0.y + w01 * f1.y + w02 * f2.y + bb0, 0.f);
    o0.z = fmaxf(w00 * f0.z + w01 * f1.z + w02 * f2.z + bb0, 0.f);
    o0.w = fmaxf(w00 * f0.w + w01 * f1.w + w02 * f2.w + bb0, 0.f);

    o1.x = fmaxf(w10 * f0.x + w11 * f1.x + w12 * f2.x + bb1, 0.f);
    o1.y = fmaxf(w10 * f0.y + w11 * f1.y + w12 * f2.y + bb1, 0.f);
    o1.z = fmaxf(w10 * f0.z + w11 * f1.z + w12 * f2.z + bb1, 0.f);
    o1.w = fmaxf(w10 * f0.w + w11 * f1.w + w12 * f2.w + bb1, 0.f);

    o2.x = fmaxf(w20 * f0.x + w21 * f1.x + w22 * f2.x + bb2, 0.f);
    o2.y = fmaxf(w20 * f0.y + w21 * f1.y + w22 * f2.y + bb2, 0.f);
    o2.z = fmaxf(w20 * f0.z + w21 * f1.z + w22 * f2.z + bb2, 0.f);
    o2.w = fmaxf(w20 * f0.w + w21 * f1.w + w22 * f2.w + bb2, 0.f);

    // ---- streaming stores ----
    float* ob = out + (long)b * 3 * plane;
    const long XM_OFF = 48L * plane;
    const long YM_OFF = 64L * plane;

    __stcs((float4*)(ob + 0 * plane + pix), o0);
    __stcs((float4*)(ob + 1 * plane + pix), o1);
    __stcs((float4*)(ob + 2 * plane + pix), o2);
    __stcs((float4*)(out + XM_OFF + (long)b * plane + pix), xm);
    __stcs((float4*)(out + YM_OFF + (long)b * plane + pix), ym);
}

extern "C" void kernel_launch(void* const* d_in, const int* in_sizes, int n_in,
                              void* d_out, int out_size)
{
    const float* mask = (const float*)d_in[0];
    const float* xl   = (const float*)d_in[1];
    const float* yl   = (const float*)d_in[2];
    const float* cw   = (const float*)d_in[3];
    const float* cb   = (const float*)d_in[4];
    float* out = (float*)d_out;

    // 16 * 1024 * 256 threads total, 256 per block -> 16384 blocks
    const int total = 16 * 1024 * 256;
    fused_upsample_blend_conv<<<total / 256, 256>>>(mask, xl, yl, cw, cb, out);
}

// round 10
// speedup vs baseline: 1.0014x; 1.0014x over previous
#include <cuda_runtime.h>

// B=16, mask (16,2,512,512) -bilinear x2-> (16,2,1024,1024)
// fused = x_mask*xl + y_mask*yl (3 ch), out = relu(conv1x1(fused)+b)
// d_out: out (48 planes) | x_mask (16 planes) | y_mask (16 planes), plane=1024*1024
//
// Locked config (R2-R9 sweep): one float4 group/thread, 6 CTAs/SM (regs 40,
// occ ~64%), __ldcs reads, float2 mask pair-loads. Plateau: 110us, 82% DRAM.
// R10 experiment: stores via __stwt (write-through) instead of __stcs —
// keeps 320MiB of write data out of L2 allocation, steadier DRAM write
// cadence vs eviction bursts. Only remaining untested cache-policy knob.

#define HS 512
#define WS 512
#define HU 1024
#define WU 1024

__global__ __launch_bounds__(256, 6)
void fused_upsample_blend_conv(const float* __restrict__ mask,
                               const float* __restrict__ xl,
                               const float* __restrict__ yl,
                               const float* __restrict__ cw,
                               const float* __restrict__ cb,
                               float* __restrict__ out)
{
    const int idx = blockIdx.x * blockDim.x + threadIdx.x;
    // idx -> (b, h, w4): w4 in [0,256), h in [0,1024), b in [0,16)
    const int w4 = idx & 255;
    const int h  = (idx >> 8) & 1023;
    const int b  = idx >> 18;

    const int w = w4 << 2;
    const long plane = (long)HU * WU;
    const long pix   = (long)h * WU + w;
    const float* xb = xl + (long)b * 3 * plane;
    const float* yb = yl + (long)b * 3 * plane;

    // ---- streaming loads first (touched once; evict-first) ----
    const float4 a0 = __ldcs((const float4*)(xb + 0 * plane + pix));
    const float4 a1 = __ldcs((const float4*)(xb + 1 * plane + pix));
    const float4 a2 = __ldcs((const float4*)(xb + 2 * plane + pix));
    const float4 g0 = __ldcs((const float4*)(yb + 0 * plane + pix));
    const float4 g1 = __ldcs((const float4*)(yb + 1 * plane + pix));
    const float4 g2 = __ldcs((const float4*)(yb + 2 * plane + pix));

    // ---- bilinear mask upsample (half-pixel centers, scale 2) ----
    // row h samples source row 0.5h-0.25:
    //   even h=2j: 0.75*row[j] + 0.25*row[j-1] (clamped)
    //   odd  h=2j+1: 0.75*row[j] + 0.25*row[j+1] (clamped)
    const int hj = h >> 1;
    const int r1 = hj;
    const int r2 = (h & 1) ? min(hj + 1, HS - 1) : max(hj - 1, 0);

    const int k0  = w4 << 1;              // even, 0..510
    const int cm1 = max(k0 - 1, 0);
    const int cp2 = min(k0 + 2, WS - 1);

    const float* m0r1 = mask + (((long)b * 2 + 0) * HS + r1) * WS;
    const float* m0r2 = mask + (((long)b * 2 + 0) * HS + r2) * WS;
    const float* m1r1 = mask + (((long)b * 2 + 1) * HS + r1) * WS;
    const float* m1r2 = mask + (((long)b * 2 + 1) * HS + r2) * WS;

    // pair loads: (k0, k0+1) is an aligned float2 (k0 even)
    const float2 p01 = __ldg((const float2*)(m0r1 + k0));
    const float2 p02 = __ldg((const float2*)(m0r2 + k0));
    const float2 p11 = __ldg((const float2*)(m1r1 + k0));
    const float2 p12 = __ldg((const float2*)(m1r2 + k0));

    // vertical interp at 4 source columns, both mask channels (L1/L2-resident)
    const float v0a = 0.75f * __ldg(m0r1 + cm1) + 0.25f * __ldg(m0r2 + cm1);
    const float v0b = 0.75f * p01.x + 0.25f * p02.x;
    const float v0c = 0.75f * p01.y + 0.25f * p02.y;
    const float v0d = 0.75f * __ldg(m0r1 + cp2) + 0.25f * __ldg(m0r2 + cp2);

    const float v1a = 0.75f * __ldg(m1r1 + cm1) + 0.25f * __ldg(m1r2 + cm1);
    const float v1b = 0.75f * p11.x + 0.25f * p12.x;
    const float v1c = 0.75f * p11.y + 0.25f * p12.y;
    const float v1d = 0.75f * __ldg(m1r1 + cp2) + 0.25f * __ldg(m1r2 + cp2);

    // horizontal: out 2k -> .75 v[k] + .25 v[k-1]; out 2k+1 -> .75 v[k] + .25 v[k+1]
    float4 xm, ym;
    xm.x = 0.75f * v0b + 0.25f * v0a;
    xm.y = 0.75f * v0b + 0.25f * v0c;
    xm.z = 0.75f * v0c + 0.25f * v0b;
    xm.w = 0.75f * v0c + 0.25f * v0d;

    ym.x = 0.75f * v1b + 0.25f * v1a;
    ym.y = 0.75f * v1b + 0.25f * v1c;
    ym.z = 0.75f * v1c + 0.25f * v1b;
    ym.w = 0.75f * v1c + 0.25f * v1d;

    // ---- fuse (consumes the DRAM loads) ----
    float4 f0, f1, f2;
    f0.x = xm.x * a0.x + ym.x * g0.x;  f0.y = xm.y * a0.y + ym.y * g0.y;
    f0.z = xm.z * a0.z + ym.z * g0.z;  f0.w = xm.w * a0.w + ym.w * g0.w;
    f1.x = xm.x * a1.x + ym.x * g1.x;  f1.y = xm.y * a1.y + ym.y * g1.y;
    f1.z = xm.z * a1.z + ym.z * g1.z;  f1.w = xm.w * a1.w + ym.w * g1.w;
    f2.x = xm.x * a2.x + ym.x * g2.x;  f2.y = xm.y * a2.y + ym.y * g2.y;
    f2.z = xm.z * a2.z + ym.z * g2.z;  f2.w = xm.w * a2.w + ym.w * g2.w;

    // conv params (uniform broadcast, L1-resident)
    const float w00 = __ldg(cw + 0), w01 = __ldg(cw + 1), w02 = __ldg(cw + 2);
    const float w10 = __ldg(cw + 3), w11 = __ldg(cw + 4), w12 = __ldg(cw + 5);
    const float w20 = __ldg(cw + 6), w21 = __ldg(cw + 7), w22 = __ldg(cw + 8);
    const float bb0 = __ldg(cb + 0), bb1 = __ldg(cb + 1), bb2 = __ldg(cb + 2);

    float4 o0, o1, o2;
    o0.x = fmaxf(w00 * f0.x + w01 * f1.x + w02 * f2.x + bb0, 0.f);
    o0.y = fmaxf(w00 * f0.y + w01 * f1.y + w02 * f2.y + bb0, 0.f);
    o0.z = fmaxf(w00 * f0.z + w01 * f1.z + w02 * f2.z + bb0, 0.f);
    o0.w = fmaxf(w00 * f0.w + w01 * f1.w + w02 * f2.w + bb0, 0.f);

    o1.x = fmaxf(w10 * f0.x + w11 * f1.x + w12 * f2.x + bb1, 0.f);
    o1.y = fmaxf(w10 * f0.y + w11 * f1.y + w12 * f2.y + bb1, 0.f);
    o1.z = fmaxf(w10 * f0.z + w11 * f1.z + w12 * f2.z + bb1, 0.f);
    o1.w = fmaxf(w10 * f0.w + w11 * f1.w + w12 * f2.w + bb1, 0.f);

    o2.x = fmaxf(w20 * f0.x + w21 * f1.x + w22 * f2.x + bb2, 0.f);
    o2.y = fmaxf(w20 * f0.y + w21 * f1.y + w22 * f2.y + bb2, 0.f);
    o2.z = fmaxf(w20 * f0.z + w21 * f1.z + w22 * f2.z + bb2, 0.f);
    o2.w = fmaxf(w20 * f0.w + w21 * f1.w + w22 * f2.w + bb2, 0.f);

    // ---- write-through stores (bypass L2 allocation) ----
    float* ob = out + (long)b * 3 * plane;
    const long XM_OFF = 48L * plane;
    const long YM_OFF = 64L * plane;

    __stwt((float4*)(ob + 0 * plane + pix), o0);
    __stwt((float4*)(ob + 1 * plane + pix), o1);
    __stwt((float4*)(ob + 2 * plane + pix), o2);
    __stwt((float4*)(out + XM_OFF + (long)b * plane + pix), xm);
    __stwt((float4*)(out + YM_OFF + (long)b * plane + pix), ym);
}

extern "C" void kernel_launch(void* const* d_in, const int* in_sizes, int n_in,
                              void* d_out, int out_size)
{
    const float* mask = (const float*)d_in[0];
    const float* xl   = (const float*)d_in[1];
    const float* yl   = (const float*)d_in[2];
    const float* cw   = (const float*)d_in[3];
    const float* cb   = (const float*)d_in[4];
    float* out = (float*)d_out;

    // 16 * 1024 * 256 threads total, 256 per block -> 16384 blocks
    const int total = 16 * 1024 * 256;
    fused_upsample_blend_conv<<<total / 256, 256>>>(mask, xl, yl, cw, cb, out);
}

// round 13
// speedup vs baseline: 1.0111x; 1.0097x over previous
#include <cuda_runtime.h>

// B=16, mask (16,2,512,512) -bilinear x2-> (16,2,1024,1024)
// fused = x_mask*xl + y_mask*yl (3 ch), out = relu(conv1x1(fused)+b)
// d_out: out (48 planes) | x_mask (16 planes) | y_mask (16 planes), plane=1024*1024
//
// Locked per R2-R10 sweep: one float4 group/thread, ~40 regs, occ ~64%,
// __ldcs reads, float2 mask pair-loads, streaming stores.
// R11 experiment: CTA granularity 256 -> 512 threads (3 CTAs/SM, same
// occupancy & regs). Each CTA now covers 8KB-contiguous per stream instead
// of 4KB -> longer page-coherent DRAM bursts, half the CTAs to schedule.

#define HS 512
#define WS 512
#define HU 1024
#define WU 1024

__global__ __launch_bounds__(512, 3)
void fused_upsample_blend_conv(const float* __restrict__ mask,
                               const float* __restrict__ xl,
                               const float* __restrict__ yl,
                               const float* __restrict__ cw,
                               const float* __restrict__ cb,
                               float* __restrict__ out)
{
    const int idx = blockIdx.x * blockDim.x + threadIdx.x;
    // idx -> (b, h, w4): w4 in [0,256), h in [0,1024), b in [0,16)
    const int w4 = idx & 255;
    const int h  = (idx >> 8) & 1023;
    const int b  = idx >> 18;

    const int w = w4 << 2;
    const long plane = (long)HU * WU;
    const long pix   = (long)h * WU + w;
    const float* xb = xl + (long)b * 3 * plane;
    const float* yb = yl + (long)b * 3 * plane;

    // ---- streaming loads first (touched once; evict-first) ----
    const float4 a0 = __ldcs((const float4*)(xb + 0 * plane + pix));
    const float4 a1 = __ldcs((const float4*)(xb + 1 * plane + pix));
    const float4 a2 = __ldcs((const float4*)(xb + 2 * plane + pix));
    const float4 g0 = __ldcs((const float4*)(yb + 0 * plane + pix));
    const float4 g1 = __ldcs((const float4*)(yb + 1 * plane + pix));
    const float4 g2 = __ldcs((const float4*)(yb + 2 * plane + pix));

    // ---- bilinear mask upsample (half-pixel centers, scale 2) ----
    // row h samples source row 0.5h-0.25:
    //   even h=2j: 0.75*row[j] + 0.25*row[j-1] (clamped)
    //   odd  h=2j+1: 0.75*row[j] + 0.25*row[j+1] (clamped)
    const int hj = h >> 1;
    const int r1 = hj;
    const int r2 = (h & 1) ? min(hj + 1, HS - 1) : max(hj - 1, 0);

    const int k0  = w4 << 1;              // even, 0..510
    const int cm1 = max(k0 - 1, 0);
    const int cp2 = min(k0 + 2, WS - 1);

    const float* m0r1 = mask + (((long)b * 2 + 0) * HS + r1) * WS;
    const float* m0r2 = mask + (((long)b * 2 + 0) * HS + r2) * WS;
    const float* m1r1 = mask + (((long)b * 2 + 1) * HS + r1) * WS;
    const float* m1r2 = mask + (((long)b * 2 + 1) * HS + r2) * WS;

    // pair loads: (k0, k0+1) is an aligned float2 (k0 even)
    const float2 p01 = __ldg((const float2*)(m0r1 + k0));
    const float2 p02 = __ldg((const float2*)(m0r2 + k0));
    const float2 p11 = __ldg((const float2*)(m1r1 + k0));
    const float2 p12 = __ldg((const float2*)(m1r2 + k0));

    // vertical interp at 4 source columns, both mask channels (L1/L2-resident)
    const float v0a = 0.75f * __ldg(m0r1 + cm1) + 0.25f * __ldg(m0r2 + cm1);
    const float v0b = 0.75f * p01.x + 0.25f * p02.x;
    const float v0c = 0.75f * p01.y + 0.25f * p02.y;
    const float v0d = 0.75f * __ldg(m0r1 + cp2) + 0.25f * __ldg(m0r2 + cp2);

    const float v1a = 0.75f * __ldg(m1r1 + cm1) + 0.25f * __ldg(m1r2 + cm1);
    const float v1b = 0.75f * p11.x + 0.25f * p12.x;
    const float v1c = 0.75f * p11.y + 0.25f * p12.y;
    const float v1d = 0.75f * __ldg(m1r1 + cp2) + 0.25f * __ldg(m1r2 + cp2);

    // horizontal: out 2k -> .75 v[k] + .25 v[k-1]; out 2k+1 -> .75 v[k] + .25 v[k+1]
    float4 xm, ym;
    xm.x = 0.75f * v0b + 0.25f * v0a;
    xm.y = 0.75f * v0b + 0.25f * v0c;
    xm.z = 0.75f * v0c + 0.25f * v0b;
    xm.w = 0.75f * v0c + 0.25f * v0d;

    ym.x = 0.75f * v1b + 0.25f * v1a;
    ym.y = 0.75f * v1b + 0.25f * v1c;
    ym.z = 0.75f * v1c + 0.25f * v1b;
    ym.w = 0.75f * v1c + 0.25f * v1d;

    // ---- fuse (consumes the DRAM loads) ----
    float4 f0, f1, f2;
    f0.x = xm.x * a0.x + ym.x * g0.x;  f0.y = xm.y * a0.y + ym.y * g0.y;
    f0.z = xm.z * a0.z + ym.z * g0.z;  f0.w = xm.w * a0.w + ym.w * g0.w;
    f1.x = xm.x * a1.x + ym.x * g1.x;  f1.y = xm.y * a1.y + ym.y * g1.y;
    f1.z = xm.z * a1.z + ym.z * g1.z;  f1.w = xm.w * a1.w + ym.w * g1.w;
    f2.x = xm.x * a2.x + ym.x * g2.x;  f2.y = xm.y * a2.y + ym.y * g2.y;
    f2.z = xm.z * a2.z + ym.z * g2.z;  f2.w = xm.w * a2.w + ym.w * g2.w;

    // conv params (uniform broadcast, L1-resident)
    const float w00 = __ldg(cw + 0), w01 = __ldg(cw + 1), w02 = __ldg(cw + 2);
    const float w10 = __ldg(cw + 3), w11 = __ldg(cw + 4), w12 = __ldg(cw + 5);
    const float w20 = __ldg(cw + 6), w21 = __ldg(cw + 7), w22 = __ldg(cw + 8);
    const float bb0 = __ldg(cb + 0), bb1 = __ldg(cb + 1), bb2 = __ldg(cb + 2);

    float4 o0, o1, o2;
    o0.x = fmaxf(w00 * f0.x + w01 * f1.x + w02 * f2.x + bb0, 0.f);
    o0.y = fmaxf(w00 * f0.y + w01 * f1.y + w02 * f2.y + bb0, 0.f);
    o0.z = fmaxf(w00 * f0.z + w01 * f1.z + w02 * f2.z + bb0, 0.f);
    o0.w = fmaxf(w00 * f0.w + w01 * f1.w + w02 * f2.w + bb0, 0.f);

    o1.x = fmaxf(w10 * f0.x + w11 * f1.x + w12 * f2.x + bb1, 0.f);
    o1.y = fmaxf(w10 * f0.y + w11 * f1.y + w12 * f2.y + bb1, 0.f);
    o1.z = fmaxf(w10 * f0.z + w11 * f1.z + w12 * f2.z + bb1, 0.f);
    o1.w = fmaxf(w10 * f0.w + w11 * f1.w + w12 * f2.w + bb1, 0.f);

    o2.x = fmaxf(w20 * f0.x + w21 * f1.x + w22 * f2.x + bb2, 0.f);
    o2.y = fmaxf(w20 * f0.y + w21 * f1.y + w22 * f2.y + bb2, 0.f);
    o2.z = fmaxf(w20 * f0.z + w21 * f1.z + w22 * f2.z + bb2, 0.f);
    o2.w = fmaxf(w20 * f0.w + w21 * f1.w + w22 * f2.w + bb2, 0.f);

    // ---- streaming stores ----
    float* ob = out + (long)b * 3 * plane;
    const long XM_OFF = 48L * plane;
    const long YM_OFF = 64L * plane;

    __stcs((float4*)(ob + 0 * plane + pix), o0);
    __stcs((float4*)(ob + 1 * plane + pix), o1);
    __stcs((float4*)(ob + 2 * plane + pix), o2);
    __stcs((float4*)(out + XM_OFF + (long)b * plane + pix), xm);
    __stcs((float4*)(out + YM_OFF + (long)b * plane + pix), ym);
}

extern "C" void kernel_launch(void* const* d_in, const int* in_sizes, int n_in,
                              void* d_out, int out_size)
{
    const float* mask = (const float*)d_in[0];
    const float* xl   = (const float*)d_in[1];
    const float* yl   = (const float*)d_in[2];
    const float* cw   = (const float*)d_in[3];
    const float* cb   = (const float*)d_in[4];
    float* out = (float*)d_out;

    // 16 * 1024 * 256 threads total, 512 per block -> 8192 blocks
    const int total = 16 * 1024 * 256;
    fused_upsample_blend_conv<<<total / 512, 512>>>(mask, xl, yl, cw, cb, out);
}